// round 4
// baseline (speedup 1.0000x reference)
#include <cuda_runtime.h>
#include <cuda_bf16.h>
#include <cstdint>

#define H_FEATS 128
#define D2 256
#define LN_EPS 1e-5f
#define MAX_NODES 262144

// Node table: x=sum(h), y=sum(h^2), z=dot(h, gW[0:128]), w=dot(h, gW[128:256])
__device__ float4 g_node_tab[MAX_NODES];

// ---------------------------------------------------------------------------
// Kernel 1: per-node stats. One warp per node (float4/lane = 128 floats).
// Each block rebuilds gW = gamma*W in smem (2KB of L2-hit loads — free).
// ---------------------------------------------------------------------------
__global__ void __launch_bounds__(256) node_stats_kernel(
        const float* __restrict__ h,
        const float* __restrict__ gamma,
        const float* __restrict__ W,
        int n_nodes) {
    __shared__ float4 sgW[64];   // gW as 64 float4s

    int t = threadIdx.x;
    // build gW in smem (256 threads, one element each)
    {
        float gw = gamma[t] * W[t];
        reinterpret_cast<float*>(sgW)[t] = gw;
    }
    __syncthreads();

    int gtid = blockIdx.x * blockDim.x + t;
    int node = gtid >> 5;
    int lane = t & 31;
    if (node >= n_nodes) return;

    const float4* row = reinterpret_cast<const float4*>(h + (size_t)node * H_FEATS);
    float4 v = __ldg(row + lane);

    float4 g0 = sgW[lane];        // gW[lane*4 .. +3]     (src half)
    float4 g1 = sgW[lane + 32];   // gW[128 + lane*4 ..]  (dst half)

    float s1 = v.x + v.y + v.z + v.w;
    float s2 = v.x*v.x + v.y*v.y + v.z*v.z + v.w*v.w;
    float ds = v.x*g0.x + v.y*g0.y + v.z*g0.z + v.w*g0.w;
    float dd = v.x*g1.x + v.y*g1.y + v.z*g1.z + v.w*g1.w;

    #pragma unroll
    for (int off = 16; off > 0; off >>= 1) {
        s1 += __shfl_down_sync(0xFFFFFFFFu, s1, off);
        s2 += __shfl_down_sync(0xFFFFFFFFu, s2, off);
        ds += __shfl_down_sync(0xFFFFFFFFu, ds, off);
        dd += __shfl_down_sync(0xFFFFFFFFu, dd, off);
    }
    if (lane == 0) {
        g_node_tab[node] = make_float4(s1, s2, ds, dd);
    }
}

// ---------------------------------------------------------------------------
// Kernel 2: per-edge score, 4 edges per thread (int4/float4), 8 gathers in
// flight per thread. Each block rebuilds the two scalars Sgw / C from the
// 1KB param vectors (L2 hits) with a smem tree reduce.
// ---------------------------------------------------------------------------
__global__ void __launch_bounds__(256) edge_score_kernel(
        const int* __restrict__ src,
        const int* __restrict__ dst,
        float* __restrict__ out,
        int n_edges,
        const float* __restrict__ gamma,
        const float* __restrict__ beta,
        const float* __restrict__ W,
        const float* __restrict__ b) {
    __shared__ float sA[D2];
    __shared__ float sB[D2];

    int t = threadIdx.x;
    {
        float w = W[t];
        sA[t] = gamma[t] * w;
        sB[t] = beta[t] * w;
    }
    __syncthreads();
    #pragma unroll
    for (int off = 128; off > 0; off >>= 1) {
        if (t < off) { sA[t] += sA[t + off]; sB[t] += sB[t + off]; }
        __syncthreads();
    }
    const float Sgw = sA[0];
    const float C   = sB[0] + __ldg(b);

    const float inv = 1.0f / (float)D2;
    int q = blockIdx.x * blockDim.x + t;     // quad index
    int base = q * 4;

    if (base + 3 < n_edges) {
        int4 s4 = __ldg(reinterpret_cast<const int4*>(src) + q);
        int4 d4 = __ldg(reinterpret_cast<const int4*>(dst) + q);

        float4 a0 = __ldg(&g_node_tab[s4.x]);
        float4 a1 = __ldg(&g_node_tab[s4.y]);
        float4 a2 = __ldg(&g_node_tab[s4.z]);
        float4 a3 = __ldg(&g_node_tab[s4.w]);
        float4 c0 = __ldg(&g_node_tab[d4.x]);
        float4 c1 = __ldg(&g_node_tab[d4.y]);
        float4 c2 = __ldg(&g_node_tab[d4.z]);
        float4 c3 = __ldg(&g_node_tab[d4.w]);

        float4 r;
        {
            float mu = (a0.x + c0.x) * inv;
            float var = fmaf(-mu, mu, (a0.y + c0.y) * inv);
            r.x = fmaf(rsqrtf(var + LN_EPS), fmaf(-mu, Sgw, a0.z + c0.w), C);
        }
        {
            float mu = (a1.x + c1.x) * inv;
            float var = fmaf(-mu, mu, (a1.y + c1.y) * inv);
            r.y = fmaf(rsqrtf(var + LN_EPS), fmaf(-mu, Sgw, a1.z + c1.w), C);
        }
        {
            float mu = (a2.x + c2.x) * inv;
            float var = fmaf(-mu, mu, (a2.y + c2.y) * inv);
            r.z = fmaf(rsqrtf(var + LN_EPS), fmaf(-mu, Sgw, a2.z + c2.w), C);
        }
        {
            float mu = (a3.x + c3.x) * inv;
            float var = fmaf(-mu, mu, (a3.y + c3.y) * inv);
            r.w = fmaf(rsqrtf(var + LN_EPS), fmaf(-mu, Sgw, a3.z + c3.w), C);
        }
        reinterpret_cast<float4*>(out)[q] = r;
    } else if (base < n_edges) {
        for (int i = base; i < n_edges; i++) {
            int si = src[i];
            int di = dst[i];
            float4 a = __ldg(&g_node_tab[si]);
            float4 c = __ldg(&g_node_tab[di]);
            float mu = (a.x + c.x) * inv;
            float var = fmaf(-mu, mu, (a.y + c.y) * inv);
            out[i] = fmaf(rsqrtf(var + LN_EPS), fmaf(-mu, Sgw, a.z + c.w), C);
        }
    }
}

// ---------------------------------------------------------------------------
// Launch
// Inputs: 0=h [N*128] f32, 1=src [E] i32, 2=dst [E] i32,
//         3=ln_gamma [256] f32, 4=ln_beta [256] f32, 5=W [256] f32, 6=b [1] f32
// Output: [E] f32
// ---------------------------------------------------------------------------
extern "C" void kernel_launch(void* const* d_in, const int* in_sizes, int n_in,
                              void* d_out, int out_size) {
    const float* h     = (const float*)d_in[0];
    const int*   src   = (const int*)d_in[1];
    const int*   dst   = (const int*)d_in[2];
    const float* gamma = (const float*)d_in[3];
    const float* beta  = (const float*)d_in[4];
    const float* W     = (const float*)d_in[5];
    const float* b     = (const float*)d_in[6];
    float* out = (float*)d_out;

    int n_nodes = in_sizes[0] / H_FEATS;
    int n_edges = in_sizes[1];

    // one warp per node, 8 warps per block
    int nblocks = (n_nodes + 7) / 8;
    node_stats_kernel<<<nblocks, 256>>>(h, gamma, W, n_nodes);

    int nquads = (n_edges + 3) / 4;
    int eblocks = (nquads + 255) / 256;
    edge_score_kernel<<<eblocks, 256>>>(src, dst, out, n_edges, gamma, beta, W, b);
}

// round 5
// speedup vs baseline: 1.1230x; 1.1230x over previous
#include <cuda_runtime.h>
#include <cuda_bf16.h>
#include <cstdint>

#define H_FEATS 128
#define D2 256
#define LN_EPS 1e-5f
#define MAX_NODES 262144

// Node table: x=sum(h), y=sum(h^2), z=dot(h, gW[0:128]), w=dot(h, gW[128:256])
__device__ float4 g_node_tab[MAX_NODES];
__device__ float  g_Sgw;   // sum(gamma*W)
__device__ float  g_C;     // sum(beta*W) + b

// ---------------------------------------------------------------------------
// Kernel 1: per-node stats. One warp per node (float4/lane = 128 floats).
// Each block rebuilds gW = gamma*W in smem (1KB of L2-hit loads — free).
// Block 0 additionally computes the two epilogue scalars into globals.
// ---------------------------------------------------------------------------
__global__ void __launch_bounds__(256) node_stats_kernel(
        const float* __restrict__ h,
        const float* __restrict__ gamma,
        const float* __restrict__ beta,
        const float* __restrict__ W,
        const float* __restrict__ b,
        int n_nodes) {
    __shared__ float4 sgW[64];   // gW as 64 float4s

    int t = threadIdx.x;
    float w  = W[t];
    float gw = gamma[t] * w;
    reinterpret_cast<float*>(sgW)[t] = gw;

    if (blockIdx.x == 0) {
        // block 0 also reduces Sgw and C (overlaps with everyone else's work)
        __shared__ float sA[D2];
        __shared__ float sB[D2];
        sA[t] = gw;
        sB[t] = beta[t] * w;
        __syncthreads();
        #pragma unroll
        for (int off = 128; off > 0; off >>= 1) {
            if (t < off) { sA[t] += sA[t + off]; sB[t] += sB[t + off]; }
            __syncthreads();
        }
        if (t == 0) {
            g_Sgw = sA[0];
            g_C   = sB[0] + __ldg(b);
        }
    } else {
        __syncthreads();
    }

    int gtid = blockIdx.x * blockDim.x + t;
    int node = gtid >> 5;
    int lane = t & 31;
    if (node >= n_nodes) return;

    const float4* row = reinterpret_cast<const float4*>(h + (size_t)node * H_FEATS);
    float4 v = __ldg(row + lane);

    float4 g0 = sgW[lane];        // gW[lane*4 .. +3]     (src half)
    float4 g1 = sgW[lane + 32];   // gW[128 + lane*4 ..]  (dst half)

    float s1 = v.x + v.y + v.z + v.w;
    float s2 = v.x*v.x + v.y*v.y + v.z*v.z + v.w*v.w;
    float ds = v.x*g0.x + v.y*g0.y + v.z*g0.z + v.w*g0.w;
    float dd = v.x*g1.x + v.y*g1.y + v.z*g1.z + v.w*g1.w;

    #pragma unroll
    for (int off = 16; off > 0; off >>= 1) {
        s1 += __shfl_down_sync(0xFFFFFFFFu, s1, off);
        s2 += __shfl_down_sync(0xFFFFFFFFu, s2, off);
        ds += __shfl_down_sync(0xFFFFFFFFu, ds, off);
        dd += __shfl_down_sync(0xFFFFFFFFu, dd, off);
    }
    if (lane == 0) {
        g_node_tab[node] = make_float4(s1, s2, ds, dd);
    }
}

// ---------------------------------------------------------------------------
// Kernel 2: per-edge score, 2 edges per thread. No prologue — scalars come
// from device globals written by the node kernel (stream-ordered).
// ---------------------------------------------------------------------------
__global__ void __launch_bounds__(256) edge_score_kernel(
        const int* __restrict__ src,
        const int* __restrict__ dst,
        float* __restrict__ out,
        int n_edges) {
    const float Sgw = g_Sgw;
    const float C   = g_C;
    const float inv = 1.0f / (float)D2;

    int p = blockIdx.x * blockDim.x + threadIdx.x;   // pair index
    int base = p * 2;

    if (base + 1 < n_edges) {
        int2 s2i = __ldg(reinterpret_cast<const int2*>(src) + p);
        int2 d2i = __ldg(reinterpret_cast<const int2*>(dst) + p);

        float4 a0 = __ldg(&g_node_tab[s2i.x]);
        float4 c0 = __ldg(&g_node_tab[d2i.x]);
        float4 a1 = __ldg(&g_node_tab[s2i.y]);
        float4 c1 = __ldg(&g_node_tab[d2i.y]);

        float2 r;
        {
            float mu  = (a0.x + c0.x) * inv;
            float var = fmaf(-mu, mu, (a0.y + c0.y) * inv);
            r.x = fmaf(rsqrtf(var + LN_EPS), fmaf(-mu, Sgw, a0.z + c0.w), C);
        }
        {
            float mu  = (a1.x + c1.x) * inv;
            float var = fmaf(-mu, mu, (a1.y + c1.y) * inv);
            r.y = fmaf(rsqrtf(var + LN_EPS), fmaf(-mu, Sgw, a1.z + c1.w), C);
        }
        reinterpret_cast<float2*>(out)[p] = r;
    } else if (base < n_edges) {
        int i = base;
        float4 a = __ldg(&g_node_tab[src[i]]);
        float4 c = __ldg(&g_node_tab[dst[i]]);
        float mu  = (a.x + c.x) * inv;
        float var = fmaf(-mu, mu, (a.y + c.y) * inv);
        out[i] = fmaf(rsqrtf(var + LN_EPS), fmaf(-mu, Sgw, a.z + c.w), C);
    }
}

// ---------------------------------------------------------------------------
// Launch
// Inputs: 0=h [N*128] f32, 1=src [E] i32, 2=dst [E] i32,
//         3=ln_gamma [256] f32, 4=ln_beta [256] f32, 5=W [256] f32, 6=b [1] f32
// Output: [E] f32
// ---------------------------------------------------------------------------
extern "C" void kernel_launch(void* const* d_in, const int* in_sizes, int n_in,
                              void* d_out, int out_size) {
    const float* h     = (const float*)d_in[0];
    const int*   src   = (const int*)d_in[1];
    const int*   dst   = (const int*)d_in[2];
    const float* gamma = (const float*)d_in[3];
    const float* beta  = (const float*)d_in[4];
    const float* W     = (const float*)d_in[5];
    const float* b     = (const float*)d_in[6];
    float* out = (float*)d_out;

    int n_nodes = in_sizes[0] / H_FEATS;
    int n_edges = in_sizes[1];

    // one warp per node, 8 warps per block
    int nblocks = (n_nodes + 7) / 8;
    node_stats_kernel<<<nblocks, 256>>>(h, gamma, beta, W, b, n_nodes);

    int npairs = (n_edges + 1) / 2;
    int eblocks = (npairs + 255) / 256;
    edge_score_kernel<<<eblocks, 256>>>(src, dst, out, n_edges);
}

// round 6
// speedup vs baseline: 1.5045x; 1.3397x over previous
#include <cuda_runtime.h>
#include <cuda_bf16.h>
#include <cstdint>

#define H_FEATS 128
#define D2 256
#define LN_EPS 1e-5f
#define MAX_NODES 262144

// Node table: x=sum(h), y=sum(h^2), z=dot(h, gW[0:128]), w=dot(h, gW[128:256])
__device__ float4 g_node_tab[MAX_NODES];
__device__ float  g_Sgw;   // sum(gamma*W)
__device__ float  g_C;     // sum(beta*W) + b

// ---------------------------------------------------------------------------
// Kernel 1: per-node stats. 8 lanes per node, 4 float4 loads per lane (MLP=4).
// Each block rebuilds gW = gamma*W in smem. Block 0 also writes the two
// epilogue scalars.
// ---------------------------------------------------------------------------
__global__ void __launch_bounds__(256) node_stats_kernel(
        const float* __restrict__ h,
        const float* __restrict__ gamma,
        const float* __restrict__ beta,
        const float* __restrict__ W,
        const float* __restrict__ b,
        int n_nodes) {
    __shared__ float4 sgW[64];   // gW as 64 float4s

    int t = threadIdx.x;
    float w  = W[t];
    float gw = gamma[t] * w;
    reinterpret_cast<float*>(sgW)[t] = gw;

    if (blockIdx.x == 0) {
        __shared__ float sA[D2];
        __shared__ float sB[D2];
        sA[t] = gw;
        sB[t] = beta[t] * w;
        __syncthreads();
        #pragma unroll
        for (int off = 128; off > 0; off >>= 1) {
            if (t < off) { sA[t] += sA[t + off]; sB[t] += sB[t + off]; }
            __syncthreads();
        }
        if (t == 0) {
            g_Sgw = sA[0];
            g_C   = sB[0] + __ldg(b);
        }
    } else {
        __syncthreads();
    }

    int group = t >> 3;           // node within block (0..31)
    int sub   = t & 7;            // lane within node-group (0..7)
    int node  = blockIdx.x * 32 + group;
    if (node >= n_nodes) return;

    const float4* row = reinterpret_cast<const float4*>(h + (size_t)node * H_FEATS);
    // 4 independent 16B loads per lane: elements sub, sub+8, sub+16, sub+24
    float4 v0 = __ldg(row + sub);
    float4 v1 = __ldg(row + sub + 8);
    float4 v2 = __ldg(row + sub + 16);
    float4 v3 = __ldg(row + sub + 24);

    // matching gW chunks (first half for ds, second half for dd)
    float4 gl0 = sgW[sub];       float4 gh0 = sgW[32 + sub];
    float4 gl1 = sgW[sub + 8];   float4 gh1 = sgW[40 + sub];
    float4 gl2 = sgW[sub + 16];  float4 gh2 = sgW[48 + sub];
    float4 gl3 = sgW[sub + 24];  float4 gh3 = sgW[56 + sub];

    float s1 = (v0.x + v0.y + v0.z + v0.w) + (v1.x + v1.y + v1.z + v1.w)
             + (v2.x + v2.y + v2.z + v2.w) + (v3.x + v3.y + v3.z + v3.w);
    float s2 = v0.x*v0.x + v0.y*v0.y + v0.z*v0.z + v0.w*v0.w
             + v1.x*v1.x + v1.y*v1.y + v1.z*v1.z + v1.w*v1.w
             + v2.x*v2.x + v2.y*v2.y + v2.z*v2.z + v2.w*v2.w
             + v3.x*v3.x + v3.y*v3.y + v3.z*v3.z + v3.w*v3.w;
    float ds = v0.x*gl0.x + v0.y*gl0.y + v0.z*gl0.z + v0.w*gl0.w
             + v1.x*gl1.x + v1.y*gl1.y + v1.z*gl1.z + v1.w*gl1.w
             + v2.x*gl2.x + v2.y*gl2.y + v2.z*gl2.z + v2.w*gl2.w
             + v3.x*gl3.x + v3.y*gl3.y + v3.z*gl3.z + v3.w*gl3.w;
    float dd = v0.x*gh0.x + v0.y*gh0.y + v0.z*gh0.z + v0.w*gh0.w
             + v1.x*gh1.x + v1.y*gh1.y + v1.z*gh1.z + v1.w*gh1.w
             + v2.x*gh2.x + v2.y*gh2.y + v2.z*gh2.z + v2.w*gh2.w
             + v3.x*gh3.x + v3.y*gh3.y + v3.z*gh3.z + v3.w*gh3.w;

    // reduce across the 8 lanes of the group (stays within the group)
    #pragma unroll
    for (int off = 4; off > 0; off >>= 1) {
        s1 += __shfl_down_sync(0xFFFFFFFFu, s1, off);
        s2 += __shfl_down_sync(0xFFFFFFFFu, s2, off);
        ds += __shfl_down_sync(0xFFFFFFFFu, ds, off);
        dd += __shfl_down_sync(0xFFFFFFFFu, dd, off);
    }
    if (sub == 0) {
        g_node_tab[node] = make_float4(s1, s2, ds, dd);
    }
}

// ---------------------------------------------------------------------------
// Kernel 2: per-edge score, 4 edges per thread, no prologue (scalars from
// device globals written by the node kernel).
// ---------------------------------------------------------------------------
__global__ void __launch_bounds__(256) edge_score_kernel(
        const int* __restrict__ src,
        const int* __restrict__ dst,
        float* __restrict__ out,
        int n_edges) {
    const float Sgw = g_Sgw;
    const float C   = g_C;
    const float inv = 1.0f / (float)D2;

    int q = blockIdx.x * blockDim.x + threadIdx.x;   // quad index
    int base = q * 4;

    if (base + 3 < n_edges) {
        int4 s4 = __ldg(reinterpret_cast<const int4*>(src) + q);
        int4 d4 = __ldg(reinterpret_cast<const int4*>(dst) + q);

        float4 a0 = __ldg(&g_node_tab[s4.x]);
        float4 c0 = __ldg(&g_node_tab[d4.x]);
        float4 a1 = __ldg(&g_node_tab[s4.y]);
        float4 c1 = __ldg(&g_node_tab[d4.y]);
        float4 a2 = __ldg(&g_node_tab[s4.z]);
        float4 c2 = __ldg(&g_node_tab[d4.z]);
        float4 a3 = __ldg(&g_node_tab[s4.w]);
        float4 c3 = __ldg(&g_node_tab[d4.w]);

        float4 r;
        {
            float mu  = (a0.x + c0.x) * inv;
            float var = fmaf(-mu, mu, (a0.y + c0.y) * inv);
            r.x = fmaf(rsqrtf(var + LN_EPS), fmaf(-mu, Sgw, a0.z + c0.w), C);
        }
        {
            float mu  = (a1.x + c1.x) * inv;
            float var = fmaf(-mu, mu, (a1.y + c1.y) * inv);
            r.y = fmaf(rsqrtf(var + LN_EPS), fmaf(-mu, Sgw, a1.z + c1.w), C);
        }
        {
            float mu  = (a2.x + c2.x) * inv;
            float var = fmaf(-mu, mu, (a2.y + c2.y) * inv);
            r.z = fmaf(rsqrtf(var + LN_EPS), fmaf(-mu, Sgw, a2.z + c2.w), C);
        }
        {
            float mu  = (a3.x + c3.x) * inv;
            float var = fmaf(-mu, mu, (a3.y + c3.y) * inv);
            r.w = fmaf(rsqrtf(var + LN_EPS), fmaf(-mu, Sgw, a3.z + c3.w), C);
        }
        reinterpret_cast<float4*>(out)[q] = r;
    } else if (base < n_edges) {
        for (int i = base; i < n_edges; i++) {
            float4 a = __ldg(&g_node_tab[src[i]]);
            float4 c = __ldg(&g_node_tab[dst[i]]);
            float mu  = (a.x + c.x) * inv;
            float var = fmaf(-mu, mu, (a.y + c.y) * inv);
            out[i] = fmaf(rsqrtf(var + LN_EPS), fmaf(-mu, Sgw, a.z + c.w), C);
        }
    }
}

// ---------------------------------------------------------------------------
// Launch
// Inputs: 0=h [N*128] f32, 1=src [E] i32, 2=dst [E] i32,
//         3=ln_gamma [256] f32, 4=ln_beta [256] f32, 5=W [256] f32, 6=b [1] f32
// Output: [E] f32
// ---------------------------------------------------------------------------
extern "C" void kernel_launch(void* const* d_in, const int* in_sizes, int n_in,
                              void* d_out, int out_size) {
    const float* h     = (const float*)d_in[0];
    const int*   src   = (const int*)d_in[1];
    const int*   dst   = (const int*)d_in[2];
    const float* gamma = (const float*)d_in[3];
    const float* beta  = (const float*)d_in[4];
    const float* W     = (const float*)d_in[5];
    const float* b     = (const float*)d_in[6];
    float* out = (float*)d_out;

    int n_nodes = in_sizes[0] / H_FEATS;
    int n_edges = in_sizes[1];

    // 32 nodes per block (8 lanes per node)
    int nblocks = (n_nodes + 31) / 32;
    node_stats_kernel<<<nblocks, 256>>>(h, gamma, beta, W, b, n_nodes);

    int nquads = (n_edges + 3) / 4;
    int eblocks = (nquads + 255) / 256;
    edge_score_kernel<<<eblocks, 256>>>(src, dst, out, n_edges);
}